// round 3
// baseline (speedup 1.0000x reference)
#include <cuda_runtime.h>
#include <cstdint>

#define NN     100000
#define EE     1000000
#define DIN    128
#define DOUT   64
#define DEDGE  11
#define ET     (EE + NN)

// ---------------- scratch (device globals: no allocation allowed) ----------
__device__ float g_xl[NN * DOUT];          // x @ W_l   (25.6 MB)
__device__ float g_xr[NN * DOUT];          // x @ W_r   (25.6 MB)
__device__ float g_logits[ET];             // per-edge logit (4.4 MB)
__device__ float g_deg[NN];
__device__ float g_loop_attr[NN * DEDGE];
__device__ float g_denom[NN];
__device__ int   g_lmax[NN];               // ordered-int encoded float max

// ordered-int mapping: monotone in float value, supports atomicMax on int
__device__ __forceinline__ int f2o(float f) {
    int i = __float_as_int(f);
    return i >= 0 ? i : (i ^ 0x7FFFFFFF);
}
__device__ __forceinline__ float o2f(int i) {
    return __int_as_float(i >= 0 ? i : (i ^ 0x7FFFFFFF));
}

// ---------------- 0: init ---------------------------------------------------
__global__ void k_init(float* __restrict__ out) {
    int i = blockIdx.x * blockDim.x + threadIdx.x;
    if (i < NN) {
        g_deg[i]   = 0.0f;
        g_denom[i] = 0.0f;
        g_lmax[i]  = (int)0x80000000;  // INT_MIN, below any ordered value
    }
    if (i < NN * DEDGE) g_loop_attr[i] = 0.0f;
    if (i < NN * DOUT)  out[i] = 0.0f;
}

// ---------------- 1: degree + incoming-attr sums ----------------------------
__global__ void k_deg(const int* __restrict__ ei, const float* __restrict__ ea) {
    int e = blockIdx.x * blockDim.x + threadIdx.x;
    if (e >= EE) return;
    int dst = ei[EE + e];
    atomicAdd(&g_deg[dst], 1.0f);
    const float* a = ea + (size_t)e * DEDGE;
    float* la = g_loop_attr + (size_t)dst * DEDGE;
#pragma unroll
    for (int k = 0; k < DEDGE; k++) atomicAdd(&la[k], a[k]);
}

// ---------------- 2: normalize loop attrs (mean) -----------------------------
__global__ void k_norm() {
    int i = blockIdx.x * blockDim.x + threadIdx.x;
    if (i >= NN) return;
    float inv = 1.0f / fmaxf(g_deg[i], 1.0f);
#pragma unroll
    for (int k = 0; k < DEDGE; k++) g_loop_attr[i * DEDGE + k] *= inv;
}

// ---------------- 3: fused dual GEMM: xl = x@Wl, xr = x@Wr -------------------
// 256 threads: 64 d-columns x 4 row-groups, 4 rows/thread => 16 rows/tile.
// W_l + W_r resident in shared (64 KB), x tile 8 KB. Dynamic smem = 72 KB.
__global__ void __launch_bounds__(256, 2)
k_gemm(const float* __restrict__ x, const float* __restrict__ Wl,
       const float* __restrict__ Wr) {
    extern __shared__ float sm[];
    float* sWl = sm;            // 128*64
    float* sWr = sm + 8192;     // 128*64
    float* sx  = sm + 16384;    // 16*128

    {
        const float4* s = (const float4*)Wl;
        float4* d = (float4*)sWl;
        for (int i = threadIdx.x; i < 2048; i += 256) d[i] = s[i];
        s = (const float4*)Wr; d = (float4*)sWr;
        for (int i = threadIdx.x; i < 2048; i += 256) d[i] = s[i];
    }

    int dcol = threadIdx.x & 63;
    int rg   = threadIdx.x >> 6;  // 0..3
    const int ROWS = 16;
    int ntiles = NN / ROWS;       // 6250 exactly

    for (int tile = blockIdx.x; tile < ntiles; tile += gridDim.x) {
        int row0 = tile * ROWS;
        __syncthreads();
        {
            const float4* xg = (const float4*)(x + (size_t)row0 * DIN);
            float4* sx4 = (float4*)sx;
            for (int i = threadIdx.x; i < (ROWS * DIN) / 4; i += 256) sx4[i] = xg[i];
        }
        __syncthreads();

        float accl[4] = {0, 0, 0, 0};
        float accr[4] = {0, 0, 0, 0};
#pragma unroll 8
        for (int k = 0; k < DIN; k += 4) {
            float wl0 = sWl[(k + 0) * 64 + dcol];
            float wl1 = sWl[(k + 1) * 64 + dcol];
            float wl2 = sWl[(k + 2) * 64 + dcol];
            float wl3 = sWl[(k + 3) * 64 + dcol];
            float wr0 = sWr[(k + 0) * 64 + dcol];
            float wr1 = sWr[(k + 1) * 64 + dcol];
            float wr2 = sWr[(k + 2) * 64 + dcol];
            float wr3 = sWr[(k + 3) * 64 + dcol];
#pragma unroll
            for (int r = 0; r < 4; r++) {
                float4 xv = *(const float4*)&sx[(rg * 4 + r) * DIN + k];
                accl[r] = fmaf(xv.x, wl0, fmaf(xv.y, wl1, fmaf(xv.z, wl2, fmaf(xv.w, wl3, accl[r]))));
                accr[r] = fmaf(xv.x, wr0, fmaf(xv.y, wr1, fmaf(xv.z, wr2, fmaf(xv.w, wr3, accr[r]))));
            }
        }
#pragma unroll
        for (int r = 0; r < 4; r++) {
            int row = row0 + rg * 4 + r;
            g_xl[row * DOUT + dcol] = accl[r];
            g_xr[row * DOUT + dcol] = accr[r];
        }
    }
}

// ---------------- 4: per-edge logits + segment max ---------------------------
// One warp per edge (real edges then self-loops). Lane l owns d = 2l, 2l+1.
__global__ void __launch_bounds__(256)
k_logits(const int* __restrict__ ei, const float* __restrict__ ea,
         const float* __restrict__ We, const float* __restrict__ att) {
    __shared__ float sWe[DEDGE * DOUT];   // laid out row-major, read as float2
    __shared__ float sAtt[DOUT];
    for (int i = threadIdx.x; i < DEDGE * DOUT; i += 256) sWe[i] = We[i];
    if (threadIdx.x < DOUT) sAtt[threadIdx.x] = att[threadIdx.x];
    __syncthreads();

    int widx = (int)((blockIdx.x * blockDim.x + threadIdx.x) >> 5);
    int lane = threadIdx.x & 31;
    if (widx >= ET) return;

    int src, dst;
    const float* a;
    if (widx < EE) {
        src = ei[widx];
        dst = ei[EE + widx];
        a = ea + (size_t)widx * DEDGE;
    } else {
        src = dst = widx - EE;
        a = g_loop_attr + (size_t)(widx - EE) * DEDGE;
    }

    float av = (lane < DEDGE) ? a[lane] : 0.0f;

    const float2* sWe2 = (const float2*)sWe;
    float e0 = 0.0f, e1 = 0.0f;
#pragma unroll
    for (int k = 0; k < DEDGE; k++) {
        float ak = __shfl_sync(0xFFFFFFFFu, av, k);
        float2 w = sWe2[k * 32 + lane];
        e0 = fmaf(ak, w.x, e0);
        e1 = fmaf(ak, w.y, e1);
    }

    float2 xlv = ((const float2*)g_xl)[(size_t)src * 32 + lane];
    float2 xrv = ((const float2*)g_xr)[(size_t)dst * 32 + lane];
    float m0 = xlv.x + xrv.x + e0;  m0 = (m0 >= 0.0f) ? m0 : 0.2f * m0;
    float m1 = xlv.y + xrv.y + e1;  m1 = (m1 >= 0.0f) ? m1 : 0.2f * m1;

    const float2* sAtt2 = (const float2*)sAtt;
    float2 at = sAtt2[lane];
    float v = m0 * at.x + m1 * at.y;
#pragma unroll
    for (int o = 16; o > 0; o >>= 1) v += __shfl_xor_sync(0xFFFFFFFFu, v, o);

    if (lane == 0) {
        g_logits[widx] = v;
        atomicMax(&g_lmax[dst], f2o(v));
    }
}

// ---------------- 5: exp + denom + weighted scatter --------------------------
// One warp per edge. Lanes 0..15 scatter float4 via red.global.add.v4.f32.
__global__ void __launch_bounds__(256)
k_accum(const int* __restrict__ ei, float* __restrict__ out) {
    int widx = (int)((blockIdx.x * blockDim.x + threadIdx.x) >> 5);
    int lane = threadIdx.x & 31;
    if (widx >= ET) return;

    int src, dst;
    if (widx < EE) {
        src = ei[widx];
        dst = ei[EE + widx];
    } else {
        src = dst = widx - EE;
    }

    float v  = g_logits[widx];
    float mx = o2f(g_lmax[dst]);
    float ex = __expf(v - mx);

    if (lane == 0) atomicAdd(&g_denom[dst], ex);

    if (lane < 16) {
        float4 xlv = ((const float4*)g_xl)[(size_t)src * 16 + lane];
        float4 w;
        w.x = ex * xlv.x; w.y = ex * xlv.y; w.z = ex * xlv.z; w.w = ex * xlv.w;
        float* p = out + (size_t)dst * DOUT + lane * 4;
        unsigned long long gp = (unsigned long long)__cvta_generic_to_global(p);
        asm volatile("red.global.add.v4.f32 [%0], {%1,%2,%3,%4};"
                     :: "l"(gp), "f"(w.x), "f"(w.y), "f"(w.z), "f"(w.w)
                     : "memory");
    }
}

// ---------------- 6: final divide by softmax denominator ---------------------
__global__ void k_final(float* __restrict__ out) {
    int i = blockIdx.x * blockDim.x + threadIdx.x;
    if (i >= NN * DOUT) return;
    out[i] = out[i] / g_denom[i >> 6];
}

// ---------------- launch -----------------------------------------------------
extern "C" void kernel_launch(void* const* d_in, const int* in_sizes, int n_in,
                              void* d_out, int out_size) {
    const float* x   = (const float*)d_in[0];
    const int*   ei  = (const int*)  d_in[1];
    const float* ea  = (const float*)d_in[2];
    const float* Wl  = (const float*)d_in[3];
    const float* Wr  = (const float*)d_in[4];
    const float* We  = (const float*)d_in[5];
    const float* att = (const float*)d_in[6];
    float* out = (float*)d_out;

    cudaFuncSetAttribute(k_gemm, cudaFuncAttributeMaxDynamicSharedMemorySize, 73728);

    k_init  <<<(NN * DOUT + 255) / 256, 256>>>(out);
    k_deg   <<<(EE + 255) / 256, 256>>>(ei, ea);
    k_norm  <<<(NN + 255) / 256, 256>>>();
    k_gemm  <<<296, 256, 73728>>>(x, Wl, Wr);
    k_logits<<<(ET * 32 + 255) / 256, 256>>>(ei, ea, We, att);
    k_accum <<<(ET * 32 + 255) / 256, 256>>>(ei, out);
    k_final <<<(NN * DOUT + 255) / 256, 256>>>(out);
}